// round 15
// baseline (speedup 1.0000x reference)
#include <cuda_runtime.h>
#include <cuda_fp16.h>
#include <math.h>
#include <stdint.h>

// ---------------- problem constants ----------------
#define NN     30000      // nodes
#define EMAX   480000     // edges (before self loops)
#define DIN    128
#define F1     256        // H1*DH
#define F2     64         // H2*DH
#define GG     64
#define DOUT   10
#define ETOT   (EMAX + NN)

// ---------------- scratch (device globals; no allocation allowed) ----------------
__device__ __half g_xh  [NN * DIN];       // fp16 input features
__device__ __half g_w1t [2 * F1 * DIN];   // fp16 [N=512][K=128]  (W1l|W1r)^T
__device__ __half g_w2t [2 * F2 * F1];    // fp16 [N=128][K=256]  (W2l|W2r)^T
__device__ __half g_xl1h[NN * F1];        // fp16 gathered operand, layer 1
__device__ float  g_xr1 [NN * F1];
__device__ __half g_h1  [NN * F1];        // fp16: only feeds GEMM2 A
__device__ __half g_xl2h[NN * F2];        // fp16 gathered operand, layer 2
__device__ float  g_xr2 [NN * F2];
__device__ int    g_deg[NN];
__device__ int    g_row[NN + 1];
__device__ int    g_cur[NN];
__device__ int    g_csr[ETOT];
__device__ float  g_pool[GG * F2];        // raw sums (divided by count in mlp)

// ---------------- mma / cp.async / ldmatrix helpers ----------------
__device__ __forceinline__ void mma_f16(float* d, const uint32_t* a, const uint32_t* b) {
    asm("mma.sync.aligned.m16n8k16.row.col.f32.f16.f16.f32 "
        "{%0,%1,%2,%3},{%4,%5,%6,%7},{%8,%9},{%0,%1,%2,%3};"
        : "+f"(d[0]), "+f"(d[1]), "+f"(d[2]), "+f"(d[3])
        : "r"(a[0]), "r"(a[1]), "r"(a[2]), "r"(a[3]), "r"(b[0]), "r"(b[1]));
}

__device__ __forceinline__ void cp16(uint32_t smem, const void* gmem) {
    asm volatile("cp.async.cg.shared.global [%0], [%1], 16;" :: "r"(smem), "l"(gmem));
}
#define CP_COMMIT()  asm volatile("cp.async.commit_group;")
#define CP_WAIT0()   asm volatile("cp.async.wait_group 0;")

__device__ __forceinline__ void ldsm4(uint32_t* r, uint32_t saddr) {
    asm volatile("ldmatrix.sync.aligned.m8n8.x4.shared.b16 {%0,%1,%2,%3}, [%4];"
        : "=r"(r[0]), "=r"(r[1]), "=r"(r[2]), "=r"(r[3]) : "r"(saddr));
}

// ---------------- fp16 single-K-shot GEMM, 3 CTAs/SM ------------------------
// A [M,K] fp16 row-major; Bt [Nc,K] fp16 (N-major rows of K).  Nc = 2*Nn.
// C(:, 0:Nn) -> fp16 H0 ; C(:, Nn:Nc) -> fp32 C1.
// 256 thr, BM=128, BN=64, KC=128-half chunks; warps 4x2; warp tile 32x32.
// Row stride 272B: ldmatrix 8-row phases bank-conflict-free. smem 52224B.
#define ROWU 68
#define ATILEU (128 * ROWU)
__global__ void __launch_bounds__(256, 3) k_hgemm(const __half* __restrict__ A,
                                                  const __half* __restrict__ Bt,
                                                  __half* __restrict__ H0,
                                                  float* __restrict__ C1,
                                                  int M, int K, int Nn) {
    extern __shared__ uint32_t dsm[];
    uint32_t* As = dsm;
    uint32_t* Bs = dsm + ATILEU;

    int n0 = blockIdx.x * 64;
    int m0 = blockIdx.y * 128;

    int tid  = threadIdx.x;
    int wid  = tid >> 5, lane = tid & 31;
    int g    = lane >> 2, t = lane & 3;
    int wm   = wid >> 1, wn = wid & 1;      // warp grid 4x2
    int wr   = wm * 32;
    int wc   = wn * 32;

    float acc[2][4][4];
#pragma unroll
    for (int i = 0; i < 2; i++)
#pragma unroll
        for (int j = 0; j < 4; j++)
#pragma unroll
            for (int q = 0; q < 4; q++) acc[i][j][q] = 0.f;

    uint32_t sA = (uint32_t)__cvta_generic_to_shared(As);
    uint32_t sB = (uint32_t)__cvta_generic_to_shared(Bs);
    uint32_t aoff = (uint32_t)(wr + (lane & 15)) * 272u + (uint32_t)(lane >> 4) * 16u;
    uint32_t boff = (uint32_t)(wc + (lane & 7) + ((lane >> 4) << 3)) * 272u
                  + (uint32_t)((lane >> 3) & 1) * 16u;

    const int nCh = K >> 7;                  // chunks of 128 halves
    for (int ch = 0; ch < nCh; ch++) {
        int kbase = ch << 7;
        // A chunk: 128 rows x 16 chunks of 16B
#pragma unroll
        for (int p = 0; p < 8; p++) {
            int idx = p * 256 + tid;
            int r = idx >> 4, o = idx & 15;
            int gr = m0 + r; if (gr >= M) gr = M - 1;
            cp16(sA + (uint32_t)(r * ROWU + o * 4) * 4u,
                 A + (size_t)gr * K + kbase + o * 8);
        }
        // B chunk: 64 rows x 16
#pragma unroll
        for (int p = 0; p < 4; p++) {
            int idx = p * 256 + tid;
            int r = idx >> 4, o = idx & 15;
            cp16(sB + (uint32_t)(r * ROWU + o * 4) * 4u,
                 Bt + (size_t)(n0 + r) * K + kbase + o * 8);
        }
        CP_COMMIT();
        CP_WAIT0();
        __syncthreads();

#pragma unroll
        for (int ks = 0; ks < 8; ks++) {
            uint32_t kb = (uint32_t)ks * 32u;
            uint32_t af[2][4], bfr[2][4];
#pragma unroll
            for (int mt = 0; mt < 2; mt++)
                ldsm4(af[mt], sA + (uint32_t)(mt * 16) * 272u + kb + aoff);
#pragma unroll
            for (int p = 0; p < 2; p++)
                ldsm4(bfr[p], sB + (uint32_t)(p * 16) * 272u + kb + boff);
#pragma unroll
            for (int mt = 0; mt < 2; mt++)
#pragma unroll
                for (int nt = 0; nt < 4; nt++)
                    mma_f16(acc[mt][nt], af[mt], &bfr[nt >> 1][(nt & 1) * 2]);
        }
        if (ch + 1 < nCh) __syncthreads();
    }

    // epilogue: columns < Nn -> fp16 H0, else -> fp32 C1
#pragma unroll
    for (int mt = 0; mt < 2; mt++) {
        int r0 = m0 + wr + mt * 16 + g;
        int r1 = r0 + 8;
#pragma unroll
        for (int nt = 0; nt < 4; nt++) {
            int cc = n0 + wc + nt * 8 + t * 2;
            if (cc < Nn) {
                __half2 h01 = __floats2half2_rn(acc[mt][nt][0], acc[mt][nt][1]);
                __half2 h23 = __floats2half2_rn(acc[mt][nt][2], acc[mt][nt][3]);
                if (r0 < M) *(__half2*)(H0 + (size_t)r0 * Nn + cc) = h01;
                if (r1 < M) *(__half2*)(H0 + (size_t)r1 * Nn + cc) = h23;
            } else {
                int c2 = cc - Nn;
                if (r0 < M)
                    *(float2*)(C1 + (size_t)r0 * Nn + c2) = make_float2(acc[mt][nt][0], acc[mt][nt][1]);
                if (r1 < M)
                    *(float2*)(C1 + (size_t)r1 * Nn + c2) = make_float2(acc[mt][nt][2], acc[mt][nt][3]);
            }
        }
    }
}

// ---------------- fused prep: x->fp16, weights->fp16 transposed, degree hist --
__global__ void k_prep(const float* __restrict__ x,
                       const float* __restrict__ W1l, const float* __restrict__ W1r,
                       const float* __restrict__ W2l, const float* __restrict__ W2r,
                       const int* __restrict__ ei, int E) {
    const int NX  = NN * DIN / 8;          // 480000 (8 elems per thread)
    const int SZ1 = 2 * F1 * DIN;          // 65536
    const int SZ2 = 2 * F2 * F1;           // 32768
    int i = blockIdx.x * blockDim.x + threadIdx.x;
    if (i < NX) {
        float4 v0 = *(const float4*)(x + (size_t)i * 8);
        float4 v1 = *(const float4*)(x + (size_t)i * 8 + 4);
        __half2 h0 = __floats2half2_rn(v0.x, v0.y);
        __half2 h1 = __floats2half2_rn(v0.z, v0.w);
        __half2 h2 = __floats2half2_rn(v1.x, v1.y);
        __half2 h3 = __floats2half2_rn(v1.z, v1.w);
        uint4 u = make_uint4(*(uint32_t*)&h0, *(uint32_t*)&h1,
                             *(uint32_t*)&h2, *(uint32_t*)&h3);
        *(uint4*)(g_xh + (size_t)i * 8) = u;
    } else if (i < NX + SZ1) {
        int j = i - NX;
        int n = j / DIN, k = j - n * DIN;
        float v = (n < F1) ? W1l[(size_t)k * F1 + n] : W1r[(size_t)k * F1 + (n - F1)];
        g_w1t[j] = __float2half_rn(v);
    } else if (i < NX + SZ1 + SZ2) {
        int j = i - NX - SZ1;
        int n = j / F1, k = j - n * F1;
        float v = (n < F2) ? W2l[(size_t)k * F2 + n] : W2r[(size_t)k * F2 + (n - F2)];
        g_w2t[j] = __float2half_rn(v);
    } else if (i < NX + SZ1 + SZ2 + E) {
        int e = i - NX - SZ1 - SZ2;
        atomicAdd(&g_deg[ei[E + e]], 1);
    }
}

// ---------------- CSR build ----------------
// 1024-thread shuffle scan (+1 self loop folded in) fused with csr_init
__global__ void k_scan(int n) {
    __shared__ int wsum[32];
    __shared__ int carry;
    int tid = threadIdx.x, lane = tid & 31, wid = tid >> 5;
    if (tid == 0) carry = 0;
    __syncthreads();
    for (int base = 0; base < n; base += 1024) {
        int i = base + tid;
        int v = (i < n) ? (g_deg[i] + 1) : 0;     // +1 = self loop
        int incl = v;
#pragma unroll
        for (int off = 1; off < 32; off <<= 1) {
            int tt = __shfl_up_sync(0xffffffffu, incl, off);
            if (lane >= off) incl += tt;
        }
        if (lane == 31) wsum[wid] = incl;
        __syncthreads();
        if (wid == 0) {
            int s = wsum[lane];
#pragma unroll
            for (int off = 1; off < 32; off <<= 1) {
                int tt = __shfl_up_sync(0xffffffffu, s, off);
                if (lane >= off) s += tt;
            }
            wsum[lane] = s;
        }
        __syncthreads();
        int woff = wid ? wsum[wid - 1] : 0;
        int c = carry;
        if (i < n) {
            int r = c + woff + incl - v;          // exclusive
            g_row[i] = r;
            g_csr[r] = i;                          // self loop first
            g_cur[i] = r + 1;
        }
        __syncthreads();
        if (tid == 0) carry = c + wsum[31];
        __syncthreads();
    }
    if (tid == 0) g_row[n] = carry;
}

__global__ void k_scatter(const int* __restrict__ ei, int E) {
    int e = blockIdx.x * blockDim.x + threadIdx.x;
    if (e < E) {
        int dst = ei[E + e];
        int pos = atomicAdd(&g_cur[dst], 1);
        g_csr[pos] = ei[e];
    }
}

// ---------------- GATv2 aggregation, layer 1 (2-deep pipeline) ---------------
__global__ void k_agg1(const float* __restrict__ att, const float* __restrict__ bias) {
    int warp = (blockIdx.x * blockDim.x + threadIdx.x) >> 5;
    if (warp >= NN) return;
    int lane = threadIdx.x & 31;
    int base = (lane >> 2) * 32 + (lane & 3) * 8;

    float xr[8], av[8];
    {
        float4 r0 = *(const float4*)(g_xr1 + (size_t)warp * F1 + base);
        float4 r1 = *(const float4*)(g_xr1 + (size_t)warp * F1 + base + 4);
        xr[0]=r0.x; xr[1]=r0.y; xr[2]=r0.z; xr[3]=r0.w;
        xr[4]=r1.x; xr[5]=r1.y; xr[6]=r1.z; xr[7]=r1.w;
        float4 a0 = *(const float4*)(att + base);
        float4 a1 = *(const float4*)(att + base + 4);
        av[0]=a0.x; av[1]=a0.y; av[2]=a0.z; av[3]=a0.w;
        av[4]=a1.x; av[5]=a1.y; av[6]=a1.z; av[7]=a1.w;
    }

    float acc[8];
#pragma unroll
    for (int j = 0; j < 8; j++) acc[j] = 0.f;
    float z = 0.f;

    const __half* xb = g_xl1h + base;
    int e0 = g_row[warp], e1 = g_row[warp + 1];
    uint4 b0, b1;
    b0 = *(const uint4*)(xb + (size_t)g_csr[e0] * F1);
    if (e0 + 1 < e1) b1 = *(const uint4*)(xb + (size_t)g_csr[e0 + 1] * F1);
    for (int e = e0; e < e1; e++) {
        uint4 u = b0;
        b0 = b1;
        if (e + 2 < e1)
            b1 = *(const uint4*)(xb + (size_t)g_csr[e + 2] * F1);
        __half2* hh = (__half2*)&u;
        float2 p0 = __half22float2(hh[0]);
        float2 p1 = __half22float2(hh[1]);
        float2 p2 = __half22float2(hh[2]);
        float2 p3 = __half22float2(hh[3]);
        float xj[8] = {p0.x, p0.y, p1.x, p1.y, p2.x, p2.y, p3.x, p3.y};
        float t = 0.f;
#pragma unroll
        for (int j = 0; j < 8; j++) {
            float v = xj[j] + xr[j];
            v = (v > 0.f) ? v : 0.2f * v;
            t = fmaf(v, av[j], t);
        }
        t += __shfl_xor_sync(0xffffffffu, t, 1);
        t += __shfl_xor_sync(0xffffffffu, t, 2);
        float w = __expf(t);
        z += w;
#pragma unroll
        for (int j = 0; j < 8; j++)
            acc[j] = fmaf(w, xj[j], acc[j]);
    }
    float inv = 1.f / z;
    float o[8];
#pragma unroll
    for (int j = 0; j < 8; j++) {
        float v = acc[j] * inv + bias[base + j];
        o[j] = (v > 0.f) ? v : expm1f(v);          // ELU fused
    }
    __half2 h0 = __floats2half2_rn(o[0], o[1]);
    __half2 h1 = __floats2half2_rn(o[2], o[3]);
    __half2 h2 = __floats2half2_rn(o[4], o[5]);
    __half2 h3 = __floats2half2_rn(o[6], o[7]);
    uint4 uo = make_uint4(*(uint32_t*)&h0, *(uint32_t*)&h1,
                          *(uint32_t*)&h2, *(uint32_t*)&h3);
    *(uint4*)(g_h1 + (size_t)warp * F1 + base) = uo;
}

// ---------------- GATv2 aggregation, layer 2 + fused pool accumulate ---------
__global__ void k_agg2(const float* __restrict__ att, const float* __restrict__ bias,
                       const int* __restrict__ batch) {
    int warp = (blockIdx.x * blockDim.x + threadIdx.x) >> 5;
    if (warp >= NN) return;
    int lane = threadIdx.x & 31;
    int base = (lane >> 4) * 32 + (lane & 15) * 2;

    float2 xr = *(const float2*)(g_xr2 + (size_t)warp * F2 + base);
    float2 av = *(const float2*)(att + base);

    float acc0 = 0.f, acc1 = 0.f, z = 0.f;

    const __half* xb = g_xl2h + base;
    int e0 = g_row[warp], e1 = g_row[warp + 1];
    __half2 b0, b1;
    b0 = *(const __half2*)(xb + (size_t)g_csr[e0] * F2);
    if (e0 + 1 < e1) b1 = *(const __half2*)(xb + (size_t)g_csr[e0 + 1] * F2);
    for (int e = e0; e < e1; e++) {
        float2 xj = __half22float2(b0);
        b0 = b1;
        if (e + 2 < e1)
            b1 = *(const __half2*)(xb + (size_t)g_csr[e + 2] * F2);
        float v0 = xj.x + xr.x; v0 = (v0 > 0.f) ? v0 : 0.2f * v0;
        float v1 = xj.y + xr.y; v1 = (v1 > 0.f) ? v1 : 0.2f * v1;
        float t = fmaf(v0, av.x, v1 * av.y);
        t += __shfl_xor_sync(0xffffffffu, t, 1);
        t += __shfl_xor_sync(0xffffffffu, t, 2);
        t += __shfl_xor_sync(0xffffffffu, t, 4);
        t += __shfl_xor_sync(0xffffffffu, t, 8);
        float w = __expf(t);
        z += w;
        acc0 = fmaf(w, xj.x, acc0);
        acc1 = fmaf(w, xj.y, acc1);
    }
    float inv = 1.f / z;
    float o0 = acc0 * inv + bias[base + 0];
    float o1 = acc1 * inv + bias[base + 1];
    int grp = batch[warp];
    atomicAdd(&g_pool[grp * F2 + base + 0], o0);
    atomicAdd(&g_pool[grp * F2 + base + 1], o1);
}

// ---------------- MLP head (divides pooled sums by graph counts) -------------
__device__ __forceinline__ int lb(const int* b, int n, int g) {
    int lo = 0, hi = n;
    while (lo < hi) { int mid = (lo + hi) >> 1; if (b[mid] < g) lo = mid + 1; else hi = mid; }
    return lo;
}

__global__ void k_mlp(const int* __restrict__ batch,
                      const float* __restrict__ fc1w, const float* __restrict__ fc1b,
                      const float* __restrict__ fc2w, const float* __restrict__ fc2b,
                      const float* __restrict__ fcw,  const float* __restrict__ fcb,
                      float* __restrict__ out) {
    __shared__ float hg[GG * 64];
    __shared__ float x1[GG * 32];
    __shared__ float x2[GG * 16];
    __shared__ float cinv[GG];
    int tid = threadIdx.x;
    if (tid < GG) {
        int s = lb(batch, NN, tid);
        int e = lb(batch, NN, tid + 1);
        int cnt = e - s; if (cnt < 1) cnt = 1;
        cinv[tid] = 1.f / (float)cnt;
    }
    __syncthreads();
    for (int i = tid; i < GG * 64; i += 256) hg[i] = g_pool[i] * cinv[i >> 6];
    __syncthreads();
    for (int i = tid; i < GG * 32; i += 256) {
        int g = i >> 5, o = i & 31;
        float s = fc1b[o];
        for (int k = 0; k < 64; k++) s = fmaf(hg[g * 64 + k], fc1w[k * 32 + o], s);
        x1[i] = fmaxf(s, 0.f);
    }
    __syncthreads();
    for (int i = tid; i < GG * 16; i += 256) {
        int g = i >> 4, o = i & 15;
        float s = fc2b[o];
        for (int k = 0; k < 32; k++) s = fmaf(x1[g * 32 + k], fc2w[k * 16 + o], s);
        float v = fmaxf(s, 0.f);
        x2[i] = v;
        out[GG * DOUT + i] = v;
    }
    __syncthreads();
    for (int i = tid; i < GG * DOUT; i += 256) {
        int g = i / DOUT, o = i - g * DOUT;
        float s = fcb[o];
        for (int k = 0; k < 16; k++) s = fmaf(x2[g * 16 + k], fcw[k * DOUT + o], s);
        out[i] = s;
    }
}

// ---------------- launch ----------------
extern "C" void kernel_launch(void* const* d_in, const int* in_sizes, int n_in,
                              void* d_out, int out_size) {
    const float* x    = (const float*)d_in[0];
    const int*   ei   = (const int*)  d_in[1];
    const int*   bat  = (const int*)  d_in[2];
    const float* W1l  = (const float*)d_in[3];
    const float* W1r  = (const float*)d_in[4];
    const float* a1   = (const float*)d_in[5];
    const float* b1   = (const float*)d_in[6];
    const float* W2l  = (const float*)d_in[7];
    const float* W2r  = (const float*)d_in[8];
    const float* a2   = (const float*)d_in[9];
    const float* b2   = (const float*)d_in[10];
    const float* fc1w = (const float*)d_in[11];
    const float* fc1b = (const float*)d_in[12];
    const float* fc2w = (const float*)d_in[13];
    const float* fc2b = (const float*)d_in[14];
    const float* fcw  = (const float*)d_in[15];
    const float* fcb  = (const float*)d_in[16];
    float* out = (float*)d_out;

    int E = in_sizes[1] / 2;

    __half *xh, *w1t, *w2t, *xl1h, *xl2h, *h1;
    float *xr1, *xr2, *pool;
    int *deg;
    cudaGetSymbolAddress((void**)&xh,   g_xh);
    cudaGetSymbolAddress((void**)&w1t,  g_w1t);
    cudaGetSymbolAddress((void**)&w2t,  g_w2t);
    cudaGetSymbolAddress((void**)&xl1h, g_xl1h);
    cudaGetSymbolAddress((void**)&xr1,  g_xr1);
    cudaGetSymbolAddress((void**)&h1,   g_h1);
    cudaGetSymbolAddress((void**)&xl2h, g_xl2h);
    cudaGetSymbolAddress((void**)&xr2,  g_xr2);
    cudaGetSymbolAddress((void**)&deg,  g_deg);
    cudaGetSymbolAddress((void**)&pool, g_pool);

    const int GRID_M = (NN + 127) / 128;   // 235
    const int NPREP  = NN * DIN / 8 + 2 * F1 * DIN + 2 * F2 * F1;  // + E at runtime
    const int SMEMSZ = (128 + 64) * ROWU * 4;  // 52224 B

    cudaFuncSetAttribute(k_hgemm, cudaFuncAttributeMaxDynamicSharedMemorySize, SMEMSZ);
    cudaMemsetAsync(deg, 0, NN * sizeof(int));
    cudaMemsetAsync(pool, 0, GG * F2 * sizeof(float));

    // launch 0: fused conversions + degree histogram
    k_prep<<<(NPREP + E + 255) / 256, 256>>>(x, W1l, W1r, W2l, W2r, ei, E);
    // launch 1-2: CSR
    k_scan<<<1, 1024>>>(NN);
    k_scatter<<<(E + 255) / 256, 256>>>(ei, E);

    // launch 3 (ncu capture window): layer 1 linear transforms
    k_hgemm<<<dim3(2 * F1 / 64, GRID_M), 256, SMEMSZ>>>(xh, w1t, xl1h, xr1, NN, DIN, F1);

    // layer 1 attention + aggregation (+ELU fused, fp16 out)
    k_agg1<<<(NN * 32 + 255) / 256, 256>>>(a1, b1);

    // layer 2 linear transforms (A = fp16 h1)
    k_hgemm<<<dim3(2 * F2 / 64, GRID_M), 256, SMEMSZ>>>(h1, w2t, xl2h, xr2, NN, F1, F2);

    // layer 2 attention + aggregation + fused pool accumulate
    k_agg2<<<(NN * 32 + 255) / 256, 256>>>(a2, b2, bat);

    // MLP head (includes mean division)
    k_mlp<<<1, 256>>>(bat, fc1w, fc1b, fc2w, fc2b, fcw, fcb, out);
}

// round 17
// speedup vs baseline: 1.0755x; 1.0755x over previous
#include <cuda_runtime.h>
#include <cuda_fp16.h>
#include <math.h>
#include <stdint.h>

// ---------------- problem constants ----------------
#define NN     30000      // nodes
#define EMAX   480000     // edges (before self loops)
#define DIN    128
#define F1     256        // H1*DH
#define F2     64         // H2*DH
#define GG     64
#define DOUT   10
#define ETOT   (EMAX + NN)

// ---------------- scratch (device globals; no allocation allowed) ----------------
__device__ __half g_xh  [NN * DIN];       // fp16 input features
__device__ __half g_w1t [2 * F1 * DIN];   // fp16 [N=512][K=128]  (W1l|W1r)^T
__device__ __half g_w2t [2 * F2 * F1];    // fp16 [N=128][K=256]  (W2l|W2r)^T
__device__ __half g_xl1h[NN * F1];        // fp16 gathered operand, layer 1
__device__ float  g_xr1 [NN * F1];
__device__ __half g_h1  [NN * F1];        // fp16: only feeds GEMM2 A
__device__ __half g_xl2h[NN * F2];        // fp16 gathered operand, layer 2
__device__ float  g_xr2 [NN * F2];
__device__ float  g_h2  [NN * F2];
__device__ int    g_deg[NN];
__device__ int    g_row[NN + 1];
__device__ int    g_cur[NN];
__device__ int    g_csr[ETOT];
__device__ float  g_pool[GG * F2];

// ---------------- mma / cp.async / ldmatrix helpers ----------------
__device__ __forceinline__ void mma_f16(float* d, const uint32_t* a, const uint32_t* b) {
    asm("mma.sync.aligned.m16n8k16.row.col.f32.f16.f16.f32 "
        "{%0,%1,%2,%3},{%4,%5,%6,%7},{%8,%9},{%0,%1,%2,%3};"
        : "+f"(d[0]), "+f"(d[1]), "+f"(d[2]), "+f"(d[3])
        : "r"(a[0]), "r"(a[1]), "r"(a[2]), "r"(a[3]), "r"(b[0]), "r"(b[1]));
}

__device__ __forceinline__ void cp16(uint32_t smem, const void* gmem) {
    asm volatile("cp.async.cg.shared.global [%0], [%1], 16;" :: "r"(smem), "l"(gmem));
}
#define CP_COMMIT()  asm volatile("cp.async.commit_group;")
#define CP_WAIT0()   asm volatile("cp.async.wait_group 0;")
#define CP_WAIT1()   asm volatile("cp.async.wait_group 1;")

__device__ __forceinline__ void ldsm4(uint32_t* r, uint32_t saddr) {
    asm volatile("ldmatrix.sync.aligned.m8n8.x4.shared.b16 {%0,%1,%2,%3}, [%4];"
        : "=r"(r[0]), "=r"(r[1]), "=r"(r[2]), "=r"(r[3]) : "r"(saddr));
}

// ---------------- fp16 split-group GEMM --------------------------------------
// A [M,K] fp16 row-major; Bt [Nc,K] fp16 (N-major rows of K).  Nc = 2*Nn.
// C(:, 0:Nn) -> fp16 H0 ; C(:, Nn:Nc) -> fp32 C1.
// BM=128, BN template (128 -> warps 2x4, tile 64x32; 64 -> warps 4x2, 32x32).
// K chunks of 128 halves loaded as TWO commit groups (k<64 | k>=64) so the
// second half's global loads overlap the first half's MMAs.
// Row stride 272B: ldmatrix 8-row phases bank-conflict-free.
#define ROWU 68
template<int BN>
__global__ void __launch_bounds__(256) k_hgemm(const __half* __restrict__ A,
                                               const __half* __restrict__ Bt,
                                               __half* __restrict__ H0,
                                               float* __restrict__ C1,
                                               int M, int K, int Nn) {
    constexpr int WN = BN / 32;          // warps along n
    constexpr int WM = 8 / WN;           // warps along m
    constexpr int MT = 128 / (WM * 16);  // m-frags per warp
    extern __shared__ uint32_t dsm[];
    uint32_t* As = dsm;
    uint32_t* Bs = dsm + 128 * ROWU;

    int n0 = blockIdx.x * BN;
    int m0 = blockIdx.y * 128;

    int tid  = threadIdx.x;
    int wid  = tid >> 5, lane = tid & 31;
    int g    = lane >> 2, t = lane & 3;
    int wm   = wid / WN, wn = wid % WN;
    int wr   = wm * (MT * 16);
    int wc   = wn * 32;

    float acc[MT][4][4];
#pragma unroll
    for (int i = 0; i < MT; i++)
#pragma unroll
        for (int j = 0; j < 4; j++)
#pragma unroll
            for (int q = 0; q < 4; q++) acc[i][j][q] = 0.f;

    uint32_t sA = (uint32_t)__cvta_generic_to_shared(As);
    uint32_t sB = (uint32_t)__cvta_generic_to_shared(Bs);
    uint32_t aoff = (uint32_t)(wr + (lane & 15)) * 272u + (uint32_t)(lane >> 4) * 16u;
    uint32_t boff = (uint32_t)(wc + (lane & 7) + ((lane >> 4) << 3)) * 272u
                  + (uint32_t)((lane >> 3) & 1) * 16u;

    const int nCh = K >> 7;                  // chunks of 128 halves
    for (int ch = 0; ch < nCh; ch++) {
        int kbase = ch << 7;
        // ---- commit group 1: first 64 halves (chunks o = 0..7) ----
#pragma unroll
        for (int p = 0; p < 4; p++) {
            int idx = p * 256 + tid;         // 0..1023 over 128 rows x 8 chunks
            int r = idx >> 3, o = idx & 7;
            int gr = m0 + r; if (gr >= M) gr = M - 1;
            cp16(sA + (uint32_t)(r * ROWU + o * 4) * 4u,
                 A + (size_t)gr * K + kbase + o * 8);
        }
#pragma unroll
        for (int p = 0; p < BN / 32; p++) {
            int idx = p * 256 + tid;         // BN rows x 8 chunks
            int r = idx >> 3, o = idx & 7;
            cp16(sB + (uint32_t)(r * ROWU + o * 4) * 4u,
                 Bt + (size_t)(n0 + r) * K + kbase + o * 8);
        }
        CP_COMMIT();
        // ---- commit group 2: second 64 halves (chunks o = 8..15) ----
#pragma unroll
        for (int p = 0; p < 4; p++) {
            int idx = p * 256 + tid;
            int r = idx >> 3, o = (idx & 7) + 8;
            int gr = m0 + r; if (gr >= M) gr = M - 1;
            cp16(sA + (uint32_t)(r * ROWU + o * 4) * 4u,
                 A + (size_t)gr * K + kbase + o * 8);
        }
#pragma unroll
        for (int p = 0; p < BN / 32; p++) {
            int idx = p * 256 + tid;
            int r = idx >> 3, o = (idx & 7) + 8;
            cp16(sB + (uint32_t)(r * ROWU + o * 4) * 4u,
                 Bt + (size_t)(n0 + r) * K + kbase + o * 8);
        }
        CP_COMMIT();

        // ---- first half compute overlaps group-2 loads ----
        CP_WAIT1();
        __syncthreads();
#pragma unroll
        for (int ks = 0; ks < 4; ks++) {
            uint32_t kb = (uint32_t)ks * 32u;
            uint32_t af[MT][4], bfr[2][4];
#pragma unroll
            for (int mt = 0; mt < MT; mt++)
                ldsm4(af[mt], sA + (uint32_t)(mt * 16) * 272u + kb + aoff);
#pragma unroll
            for (int p = 0; p < 2; p++)
                ldsm4(bfr[p], sB + (uint32_t)(p * 16) * 272u + kb + boff);
#pragma unroll
            for (int mt = 0; mt < MT; mt++)
#pragma unroll
                for (int nt = 0; nt < 4; nt++)
                    mma_f16(acc[mt][nt], af[mt], &bfr[nt >> 1][(nt & 1) * 2]);
        }
        CP_WAIT0();
        __syncthreads();
#pragma unroll
        for (int ks = 4; ks < 8; ks++) {
            uint32_t kb = (uint32_t)ks * 32u;
            uint32_t af[MT][4], bfr[2][4];
#pragma unroll
            for (int mt = 0; mt < MT; mt++)
                ldsm4(af[mt], sA + (uint32_t)(mt * 16) * 272u + kb + aoff);
#pragma unroll
            for (int p = 0; p < 2; p++)
                ldsm4(bfr[p], sB + (uint32_t)(p * 16) * 272u + kb + boff);
#pragma unroll
            for (int mt = 0; mt < MT; mt++)
#pragma unroll
                for (int nt = 0; nt < 4; nt++)
                    mma_f16(acc[mt][nt], af[mt], &bfr[nt >> 1][(nt & 1) * 2]);
        }
        if (ch + 1 < nCh) __syncthreads();
    }

    // epilogue: columns < Nn -> fp16 H0, else -> fp32 C1
#pragma unroll
    for (int mt = 0; mt < MT; mt++) {
        int r0 = m0 + wr + mt * 16 + g;
        int r1 = r0 + 8;
#pragma unroll
        for (int nt = 0; nt < 4; nt++) {
            int cc = n0 + wc + nt * 8 + t * 2;
            if (cc < Nn) {
                __half2 h01 = __floats2half2_rn(acc[mt][nt][0], acc[mt][nt][1]);
                __half2 h23 = __floats2half2_rn(acc[mt][nt][2], acc[mt][nt][3]);
                if (r0 < M) *(__half2*)(H0 + (size_t)r0 * Nn + cc) = h01;
                if (r1 < M) *(__half2*)(H0 + (size_t)r1 * Nn + cc) = h23;
            } else {
                int c2 = cc - Nn;
                if (r0 < M)
                    *(float2*)(C1 + (size_t)r0 * Nn + c2) = make_float2(acc[mt][nt][0], acc[mt][nt][1]);
                if (r1 < M)
                    *(float2*)(C1 + (size_t)r1 * Nn + c2) = make_float2(acc[mt][nt][2], acc[mt][nt][3]);
            }
        }
    }
}

// ---------------- fused prep: x->fp16, weights->fp16 transposed, degree hist --
__global__ void k_prep(const float* __restrict__ x,
                       const float* __restrict__ W1l, const float* __restrict__ W1r,
                       const float* __restrict__ W2l, const float* __restrict__ W2r,
                       const int* __restrict__ ei, int E) {
    const int NX  = NN * DIN / 8;          // 480000 (8 elems per thread)
    const int SZ1 = 2 * F1 * DIN;          // 65536
    const int SZ2 = 2 * F2 * F1;           // 32768
    int i = blockIdx.x * blockDim.x + threadIdx.x;
    if (i < NX) {
        float4 v0 = *(const float4*)(x + (size_t)i * 8);
        float4 v1 = *(const float4*)(x + (size_t)i * 8 + 4);
        __half2 h0 = __floats2half2_rn(v0.x, v0.y);
        __half2 h1 = __floats2half2_rn(v0.z, v0.w);
        __half2 h2 = __floats2half2_rn(v1.x, v1.y);
        __half2 h3 = __floats2half2_rn(v1.z, v1.w);
        uint4 u = make_uint4(*(uint32_t*)&h0, *(uint32_t*)&h1,
                             *(uint32_t*)&h2, *(uint32_t*)&h3);
        *(uint4*)(g_xh + (size_t)i * 8) = u;
    } else if (i < NX + SZ1) {
        int j = i - NX;
        int n = j / DIN, k = j - n * DIN;
        float v = (n < F1) ? W1l[(size_t)k * F1 + n] : W1r[(size_t)k * F1 + (n - F1)];
        g_w1t[j] = __float2half_rn(v);
    } else if (i < NX + SZ1 + SZ2) {
        int j = i - NX - SZ1;
        int n = j / F1, k = j - n * F1;
        float v = (n < F2) ? W2l[(size_t)k * F2 + n] : W2r[(size_t)k * F2 + (n - F2)];
        g_w2t[j] = __float2half_rn(v);
    } else if (i < NX + SZ1 + SZ2 + E) {
        int e = i - NX - SZ1 - SZ2;
        atomicAdd(&g_deg[ei[E + e]], 1);
    }
}

// ---------------- CSR build ----------------
__global__ void k_scan(int n) {
    __shared__ int wsum[32];
    __shared__ int carry;
    int tid = threadIdx.x, lane = tid & 31, wid = tid >> 5;
    if (tid == 0) carry = 0;
    __syncthreads();
    for (int base = 0; base < n; base += 1024) {
        int i = base + tid;
        int v = (i < n) ? (g_deg[i] + 1) : 0;     // +1 = self loop
        int incl = v;
#pragma unroll
        for (int off = 1; off < 32; off <<= 1) {
            int tt = __shfl_up_sync(0xffffffffu, incl, off);
            if (lane >= off) incl += tt;
        }
        if (lane == 31) wsum[wid] = incl;
        __syncthreads();
        if (wid == 0) {
            int s = wsum[lane];
#pragma unroll
            for (int off = 1; off < 32; off <<= 1) {
                int tt = __shfl_up_sync(0xffffffffu, s, off);
                if (lane >= off) s += tt;
            }
            wsum[lane] = s;
        }
        __syncthreads();
        int woff = wid ? wsum[wid - 1] : 0;
        int c = carry;
        if (i < n) {
            int r = c + woff + incl - v;          // exclusive
            g_row[i] = r;
            g_csr[r] = i;                          // self loop first
            g_cur[i] = r + 1;
        }
        __syncthreads();
        if (tid == 0) carry = c + wsum[31];
        __syncthreads();
    }
    if (tid == 0) g_row[n] = carry;
}

__global__ void k_scatter(const int* __restrict__ ei, int E) {
    int e = blockIdx.x * blockDim.x + threadIdx.x;
    if (e < E) {
        int dst = ei[E + e];
        int pos = atomicAdd(&g_cur[dst], 1);
        g_csr[pos] = ei[e];
    }
}

// ---------------- GATv2 aggregation, layer 1 (no-max softmax; fp16 I/O) ------
__global__ void k_agg1(const float* __restrict__ att, const float* __restrict__ bias) {
    int warp = (blockIdx.x * blockDim.x + threadIdx.x) >> 5;
    if (warp >= NN) return;
    int lane = threadIdx.x & 31;
    int base = (lane >> 2) * 32 + (lane & 3) * 8;

    float xr[8], av[8];
    {
        float4 r0 = *(const float4*)(g_xr1 + (size_t)warp * F1 + base);
        float4 r1 = *(const float4*)(g_xr1 + (size_t)warp * F1 + base + 4);
        xr[0]=r0.x; xr[1]=r0.y; xr[2]=r0.z; xr[3]=r0.w;
        xr[4]=r1.x; xr[5]=r1.y; xr[6]=r1.z; xr[7]=r1.w;
        float4 a0 = *(const float4*)(att + base);
        float4 a1 = *(const float4*)(att + base + 4);
        av[0]=a0.x; av[1]=a0.y; av[2]=a0.z; av[3]=a0.w;
        av[4]=a1.x; av[5]=a1.y; av[6]=a1.z; av[7]=a1.w;
    }

    float acc[8];
#pragma unroll
    for (int j = 0; j < 8; j++) acc[j] = 0.f;
    float z = 0.f;

    const __half* xb = g_xl1h + base;
    int e0 = g_row[warp], e1 = g_row[warp + 1];
    uint4 nu = *(const uint4*)(xb + (size_t)g_csr[e0] * F1);
    for (int e = e0; e < e1; e++) {
        uint4 u = nu;
        if (e + 1 < e1)
            nu = *(const uint4*)(xb + (size_t)g_csr[e + 1] * F1);
        __half2* hh = (__half2*)&u;
        float2 p0 = __half22float2(hh[0]);
        float2 p1 = __half22float2(hh[1]);
        float2 p2 = __half22float2(hh[2]);
        float2 p3 = __half22float2(hh[3]);
        float xj[8] = {p0.x, p0.y, p1.x, p1.y, p2.x, p2.y, p3.x, p3.y};
        float t = 0.f;
#pragma unroll
        for (int j = 0; j < 8; j++) {
            float v = xj[j] + xr[j];
            v = (v > 0.f) ? v : 0.2f * v;
            t = fmaf(v, av[j], t);
        }
        t += __shfl_xor_sync(0xffffffffu, t, 1);
        t += __shfl_xor_sync(0xffffffffu, t, 2);
        float w = __expf(t);
        z += w;
#pragma unroll
        for (int j = 0; j < 8; j++)
            acc[j] = fmaf(w, xj[j], acc[j]);
    }
    float inv = 1.f / z;
    float o[8];
#pragma unroll
    for (int j = 0; j < 8; j++) {
        float v = acc[j] * inv + bias[base + j];
        o[j] = (v > 0.f) ? v : expm1f(v);          // ELU fused
    }
    __half2 h0 = __floats2half2_rn(o[0], o[1]);
    __half2 h1 = __floats2half2_rn(o[2], o[3]);
    __half2 h2 = __floats2half2_rn(o[4], o[5]);
    __half2 h3 = __floats2half2_rn(o[6], o[7]);
    uint4 uo = make_uint4(*(uint32_t*)&h0, *(uint32_t*)&h1,
                          *(uint32_t*)&h2, *(uint32_t*)&h3);
    *(uint4*)(g_h1 + (size_t)warp * F1 + base) = uo;
}

// ---------------- GATv2 aggregation, layer 2 (no-max softmax; fp16 gather) ---
__global__ void k_agg2(const float* __restrict__ att, const float* __restrict__ bias) {
    int warp = (blockIdx.x * blockDim.x + threadIdx.x) >> 5;
    if (warp >= NN) return;
    int lane = threadIdx.x & 31;
    int base = (lane >> 4) * 32 + (lane & 15) * 2;

    float2 xr = *(const float2*)(g_xr2 + (size_t)warp * F2 + base);
    float2 av = *(const float2*)(att + base);

    float acc0 = 0.f, acc1 = 0.f, z = 0.f;

    const __half* xb = g_xl2h + base;
    int e0 = g_row[warp], e1 = g_row[warp + 1];
    __half2 nx = *(const __half2*)(xb + (size_t)g_csr[e0] * F2);
    for (int e = e0; e < e1; e++) {
        float2 xj = __half22float2(nx);
        if (e + 1 < e1)
            nx = *(const __half2*)(xb + (size_t)g_csr[e + 1] * F2);
        float v0 = xj.x + xr.x; v0 = (v0 > 0.f) ? v0 : 0.2f * v0;
        float v1 = xj.y + xr.y; v1 = (v1 > 0.f) ? v1 : 0.2f * v1;
        float t = fmaf(v0, av.x, v1 * av.y);
        t += __shfl_xor_sync(0xffffffffu, t, 1);
        t += __shfl_xor_sync(0xffffffffu, t, 2);
        t += __shfl_xor_sync(0xffffffffu, t, 4);
        t += __shfl_xor_sync(0xffffffffu, t, 8);
        float w = __expf(t);
        z += w;
        acc0 = fmaf(w, xj.x, acc0);
        acc1 = fmaf(w, xj.y, acc1);
    }
    float inv = 1.f / z;
    g_h2[(size_t)warp * F2 + base + 0] = acc0 * inv + bias[base + 0];
    g_h2[(size_t)warp * F2 + base + 1] = acc1 * inv + bias[base + 1];
}

// ---------------- mean pool over sorted batch ----------------
__device__ __forceinline__ int lb(const int* b, int n, int g) {
    int lo = 0, hi = n;
    while (lo < hi) { int mid = (lo + hi) >> 1; if (b[mid] < g) lo = mid + 1; else hi = mid; }
    return lo;
}

__global__ void k_pool(const int* __restrict__ batch, int n) {
    __shared__ float part[4][64];
    int g = blockIdx.x;
    int d = threadIdx.x & 63;
    int ty = threadIdx.x >> 6;
    int s = lb(batch, n, g);
    int e = lb(batch, n, g + 1);
    float sum = 0.f;
    for (int i = s + ty; i < e; i += 4) sum += g_h2[(size_t)i * F2 + d];
    part[ty][d] = sum;
    __syncthreads();
    if (ty == 0) {
        float tot = part[0][d] + part[1][d] + part[2][d] + part[3][d];
        int cnt = e - s; if (cnt < 1) cnt = 1;
        g_pool[g * F2 + d] = tot / (float)cnt;
    }
}

// ---------------- MLP head ----------------
__global__ void k_mlp(const float* __restrict__ fc1w, const float* __restrict__ fc1b,
                      const float* __restrict__ fc2w, const float* __restrict__ fc2b,
                      const float* __restrict__ fcw,  const float* __restrict__ fcb,
                      float* __restrict__ out) {
    __shared__ float hg[GG * 64];
    __shared__ float x1[GG * 32];
    __shared__ float x2[GG * 16];
    int tid = threadIdx.x;
    for (int i = tid; i < GG * 64; i += 256) hg[i] = g_pool[i];
    __syncthreads();
    for (int i = tid; i < GG * 32; i += 256) {
        int g = i >> 5, o = i & 31;
        float s = fc1b[o];
        for (int k = 0; k < 64; k++) s = fmaf(hg[g * 64 + k], fc1w[k * 32 + o], s);
        x1[i] = fmaxf(s, 0.f);
    }
    __syncthreads();
    for (int i = tid; i < GG * 16; i += 256) {
        int g = i >> 4, o = i & 15;
        float s = fc2b[o];
        for (int k = 0; k < 32; k++) s = fmaf(x1[g * 32 + k], fc2w[k * 16 + o], s);
        float v = fmaxf(s, 0.f);
        x2[i] = v;
        out[GG * DOUT + i] = v;
    }
    __syncthreads();
    for (int i = tid; i < GG * DOUT; i += 256) {
        int g = i / DOUT, o = i - g * DOUT;
        float s = fcb[o];
        for (int k = 0; k < 16; k++) s = fmaf(x2[g * 16 + k], fcw[k * DOUT + o], s);
        out[i] = s;
    }
}

// ---------------- launch ----------------
extern "C" void kernel_launch(void* const* d_in, const int* in_sizes, int n_in,
                              void* d_out, int out_size) {
    const float* x    = (const float*)d_in[0];
    const int*   ei   = (const int*)  d_in[1];
    const int*   bat  = (const int*)  d_in[2];
    const float* W1l  = (const float*)d_in[3];
    const float* W1r  = (const float*)d_in[4];
    const float* a1   = (const float*)d_in[5];
    const float* b1   = (const float*)d_in[6];
    const float* W2l  = (const float*)d_in[7];
    const float* W2r  = (const float*)d_in[8];
    const float* a2   = (const float*)d_in[9];
    const float* b2   = (const float*)d_in[10];
    const float* fc1w = (const float*)d_in[11];
    const float* fc1b = (const float*)d_in[12];
    const float* fc2w = (const float*)d_in[13];
    const float* fc2b = (const float*)d_in[14];
    const float* fcw  = (const float*)d_in[15];
    const float* fcb  = (const float*)d_in[16];
    float* out = (float*)d_out;

    int E = in_sizes[1] / 2;

    __half *xh, *w1t, *w2t, *xl1h, *xl2h, *h1;
    float *xr1, *xr2;
    int *deg;
    cudaGetSymbolAddress((void**)&xh,   g_xh);
    cudaGetSymbolAddress((void**)&w1t,  g_w1t);
    cudaGetSymbolAddress((void**)&w2t,  g_w2t);
    cudaGetSymbolAddress((void**)&xl1h, g_xl1h);
    cudaGetSymbolAddress((void**)&xr1,  g_xr1);
    cudaGetSymbolAddress((void**)&h1,   g_h1);
    cudaGetSymbolAddress((void**)&xl2h, g_xl2h);
    cudaGetSymbolAddress((void**)&xr2,  g_xr2);
    cudaGetSymbolAddress((void**)&deg,  g_deg);

    const int GRID_M = (NN + 127) / 128;   // 235
    const int NPREP  = NN * DIN / 8 + 2 * F1 * DIN + 2 * F2 * F1;  // + E at runtime
    const int SMEM128 = (128 + 128) * ROWU * 4;  // 69632 B
    const int SMEM64  = (128 + 64) * ROWU * 4;   // 52224 B

    cudaFuncSetAttribute(k_hgemm<128>, cudaFuncAttributeMaxDynamicSharedMemorySize, SMEM128);
    cudaFuncSetAttribute(k_hgemm<64>,  cudaFuncAttributeMaxDynamicSharedMemorySize, SMEM64);
    cudaMemsetAsync(deg, 0, NN * sizeof(int));

    // launch 0: fused conversions + degree histogram
    k_prep<<<(NPREP + E + 255) / 256, 256>>>(x, W1l, W1r, W2l, W2r, ei, E);
    // launch 1-2: CSR
    k_scan<<<1, 1024>>>(NN);
    k_scatter<<<(E + 255) / 256, 256>>>(ei, E);

    // launch 3 (ncu capture window): layer 1 linear transforms  (BN=128)
    k_hgemm<128><<<dim3(2 * F1 / 128, GRID_M), 256, SMEM128>>>(xh, w1t, xl1h, xr1, NN, DIN, F1);

    // layer 1 attention + aggregation (+ELU fused, fp16 out)
    k_agg1<<<(NN * 32 + 255) / 256, 256>>>(a1, b1);

    // layer 2 linear transforms (BN=64: fills the chip, 470 CTAs)
    k_hgemm<64><<<dim3(2 * F2 / 64, GRID_M), 256, SMEM64>>>(h1, w2t, xl2h, xr2, NN, F1, F2);

    // layer 2 attention + aggregation (+bias)
    k_agg2<<<(NN * 32 + 255) / 256, 256>>>(a2, b2);

    // pool + MLP head
    k_pool<<<GG, 256>>>(bat, NN);
    k_mlp<<<1, 256>>>(fc1w, fc1b, fc2w, fc2b, fcw, fcb, out);
}